// round 3
// baseline (speedup 1.0000x reference)
#include <cuda_runtime.h>
#include <math.h>

#define BB 512
#define DD 128
#define NLAT 16
#define NLAYER 4
#define NDRUG 25600
#define NENZ 153600
#define RR 64  // NL*H rows per batch

__device__ float g_lat[BB*NLAT*DD];
__device__ float g_nl [BB*NLAT*DD];
__device__ float g_qp [BB*RR*DD];
__device__ float g_u  [BB*RR*DD];
__device__ float g_ffh[BB*NLAT*2*DD];
__device__ float g_h  [BB*DD];
__device__ float g_P  [8*DD*512];
__device__ float g_M  [8*DD*512];
__device__ float g_pb [8*512];
__device__ float g_mb [8*DD];
__device__ int   g_st [2*(BB+1)];

__device__ __forceinline__ int lowb(const int* a, int n, int v){
    int lo=0, hi=n;
    while(lo<hi){int mid=(lo+hi)>>1; if(a[mid]<v) lo=mid+1; else hi=mid;}
    return lo;
}

__global__ void k_starts(const int* db, const int* eb){
    int b=threadIdx.x;
    if(b<BB){ g_st[b]=lowb(db,NDRUG,b); g_st[BB+1+b]=lowb(eb,NENZ,b); }
    if(b==0){ g_st[BB]=NDRUG; g_st[2*BB+1]=NENZ; }
    if(b<1024) g_mb[b]=0.f;
}

__global__ void k_init(const float* lat){
    int i=blockIdx.x*256+threadIdx.x;
    ((float4*)g_lat)[i]=((const float4*)lat)[i&511];
}

// weight precompute: P_h = Wqm_h^T Wk_h / sqrt(HD); M_h = Wo_h Wv_h; biases
__global__ void k_pre(const float* mwd,const float* mbd,const float* owd,const float* obd,
                      const float* mwe,const float* mbe,const float* owe,const float* obe){
    int idx=blockIdx.x, l=idx>>3, m=(idx>>2)&1, h=idx&3;
    const float* w =(m?mwe:mwd)+l*3*DD*DD;
    const float* b3=(m?mbe:mbd)+l*3*DD;
    const float* ow=(m?owe:owd)+l*DD*DD;
    const float* ob=(m?obe:obd)+l*DD;
    float* P=g_P+(l*2+m)*DD*512; float* M=g_M+(l*2+m)*DD*512;
    float* pb=g_pb+(l*2+m)*512;
    __shared__ float sA[32*128], sB[32*128];
    int tid=threadIdx.x;
    const float inv=0.17677669529663687f; // 1/sqrt(32)
    for(int i=tid;i<32*128;i+=256){int j=i>>7,c=i&127;
        sA[i]=w[(h*32+j)*DD+c]; sB[i]=w[(DD+h*32+j)*DD+c];}
    __syncthreads();
    for(int e=tid;e<128*128;e+=256){int c=e>>7,d=e&127; float s=0.f;
        #pragma unroll
        for(int j=0;j<32;j++) s+=sA[j*128+c]*sB[j*128+d];
        P[c*512+h*128+d]=s*inv;}
    if(tid<128){float s=0.f;
        for(int j=0;j<32;j++) s+=b3[h*32+j]*sB[j*128+tid];
        pb[h*128+tid]=s*inv;}
    __syncthreads();
    for(int i=tid;i<32*128;i+=256){int j=i>>7,c=i&127; sB[i]=w[(2*DD+h*32+j)*DD+c];}
    for(int i=tid;i<128*32;i+=256){int c=i>>5,j=i&31; sA[c*32+j]=ow[c*DD+h*32+j];}
    __syncthreads();
    for(int e=tid;e<128*128;e+=256){int c=e>>7,d=e&127; float s=0.f;
        #pragma unroll
        for(int j=0;j<32;j++) s+=sA[c*32+j]*sB[j*128+d];
        M[c*512+h*128+d]=s;}
    if(tid<128){float s=(h==0)?ob[tid]:0.f;
        for(int j=0;j<32;j++) s+=sA[tid*32+j]*b3[2*DD+h*32+j];
        atomicAdd(&g_mb[(l*2+m)*DD+tid],s);}
}

// layernorm: 1 warp per 128-d row
__global__ void __launch_bounds__(256) k_ln(const float* x,float* y,const float* g,const float* bb){
    int row=blockIdx.x*8+(threadIdx.x>>5), lane=threadIdx.x&31;
    float4 v=*(const float4*)(x+(size_t)row*DD+lane*4);
    float s=v.x+v.y+v.z+v.w, s2=v.x*v.x+v.y*v.y+v.z*v.z+v.w*v.w;
    #pragma unroll
    for(int o=16;o;o>>=1){s+=__shfl_xor_sync(~0u,s,o); s2+=__shfl_xor_sync(~0u,s2,o);}
    float m=s*(1.f/128.f), var=s2*(1.f/128.f)-m*m, iv=rsqrtf(var+1e-5f);
    float4 gg=*(const float4*)(g+lane*4), b4=*(const float4*)(bb+lane*4);
    float4 o;
    o.x=(v.x-m)*iv*gg.x+b4.x; o.y=(v.y-m)*iv*gg.y+b4.y;
    o.z=(v.z-m)*iv*gg.z+b4.z; o.w=(v.w-m)*iv*gg.w+b4.w;
    *(float4*)(y+(size_t)row*DD+lane*4)=o;
}

// tiled GEMM: C[r,c] (opt +=) = act(sum_k A[r,k]*W(c,k) + bias[c])
// WT=false: W[c*ldw+k] (C=A@W^T); WT=true: W[k*ldw+c]
template<bool WT,bool ACC,bool RELU>
__global__ void __launch_bounds__(256) k_gemm(const float* A,int lda,const float* W,int ldw,
                                              float* C,int ldc,const float* bias,
                                              int M,int N,int K){
    __shared__ float sA[32*68], sB[32*68];
    int rb=blockIdx.x*64, cb=blockIdx.y*64, tid=threadIdx.x;
    int tx=tid&15, ty=tid>>4;
    float acc[4][4]={};
    for(int k0=0;k0<K;k0+=32){
        #pragma unroll
        for(int it=0;it<2;it++){
            int i=tid+it*256, row=i>>3, q4=(i&7)<<2;
            float4 a4=*(const float4*)(A+(size_t)(rb+row)*lda+k0+q4);
            sA[(q4+0)*68+row]=a4.x; sA[(q4+1)*68+row]=a4.y;
            sA[(q4+2)*68+row]=a4.z; sA[(q4+3)*68+row]=a4.w;
        }
        if(!WT){
            #pragma unroll
            for(int it=0;it<2;it++){
                int i=tid+it*256, row=i>>3, q4=(i&7)<<2, c=cb+row;
                float4 w4=make_float4(0.f,0.f,0.f,0.f);
                if(c<N) w4=*(const float4*)(W+(size_t)c*ldw+k0+q4);
                sB[(q4+0)*68+row]=w4.x; sB[(q4+1)*68+row]=w4.y;
                sB[(q4+2)*68+row]=w4.z; sB[(q4+3)*68+row]=w4.w;
            }
        }else{
            #pragma unroll
            for(int it=0;it<2;it++){
                int i=tid+it*256, kr=i>>4, cc=(i&15)<<2;
                float4 w4=make_float4(0.f,0.f,0.f,0.f);
                if(cb+cc<N) w4=*(const float4*)(W+(size_t)(k0+kr)*ldw+cb+cc);
                *(float4*)&sB[kr*68+cc]=w4;
            }
        }
        __syncthreads();
        #pragma unroll 8
        for(int kk=0;kk<32;kk++){
            float4 a4=*(float4*)&sA[kk*68+ty*4];
            float4 b4=*(float4*)&sB[kk*68+tx*4];
            acc[0][0]+=a4.x*b4.x; acc[0][1]+=a4.x*b4.y; acc[0][2]+=a4.x*b4.z; acc[0][3]+=a4.x*b4.w;
            acc[1][0]+=a4.y*b4.x; acc[1][1]+=a4.y*b4.y; acc[1][2]+=a4.y*b4.z; acc[1][3]+=a4.y*b4.w;
            acc[2][0]+=a4.z*b4.x; acc[2][1]+=a4.z*b4.y; acc[2][2]+=a4.z*b4.z; acc[2][3]+=a4.z*b4.w;
            acc[3][0]+=a4.w*b4.x; acc[3][1]+=a4.w*b4.y; acc[3][2]+=a4.w*b4.z; acc[3][3]+=a4.w*b4.w;
        }
        __syncthreads();
    }
    #pragma unroll
    for(int i=0;i<4;i++){
        int r=rb+ty*4+i;
        #pragma unroll
        for(int j=0;j<4;j++){
            int c=cb+tx*4+j;
            if(c<N){
                float v=acc[i][j]+bias[c];
                if(ACC) v+=C[(size_t)r*ldc+c];
                if(RELU) v=fmaxf(v,0.f);
                C[(size_t)r*ldc+c]=v;
            }
        }
    }
}

// ragged cross-attention on raw tokens. qp/u: [B][64][128]
__global__ void __launch_bounds__(256) k_attn(const float* qp,const float* kb,const float* vb,
                                              const int* starts,float* u,int maxLen){
    extern __shared__ float sm[];
    float* sQ=sm;                // [64][128]
    float* sS=sm+RR*DD;          // [64][maxLen]
    float* sT=sS+RR*maxLen;      // [32][132]
    __shared__ float sInv[RR];
    int b=blockIdx.x, tid=threadIdx.x;
    int s0=starts[b], len=starts[b+1]-s0;
    if(len>maxLen) len=maxLen;
    const float* qpb=qp+(size_t)b*RR*DD;
    float* ub=u+(size_t)b*RR*DD;
    if(len==0){
        for(int i=tid;i<RR*DD/4;i+=256) ((float4*)ub)[i]=make_float4(0.f,0.f,0.f,0.f);
        return;
    }
    for(int i=tid;i<RR*DD/4;i+=256) ((float4*)sQ)[i]=((const float4*)qpb)[i];
    __syncthreads();
    int ty=tid>>4, tx=tid&15;
    // phase 1: scores
    for(int t0=0;t0<len;t0+=32){
        int tc=min(32,len-t0);
        for(int i=tid;i<tc*32;i+=256){
            int row=i>>5, c4=(i&31)<<2;
            *(float4*)&sT[row*132+c4]=*(const float4*)(kb+(size_t)(s0+t0+row)*DD+c4);
        }
        __syncthreads();
        float acc[4][2]={};
        #pragma unroll 8
        for(int d4=0;d4<DD;d4+=4){
            float4 k0=*(float4*)&sT[(tx*2)*132+d4];
            float4 k1=*(float4*)&sT[(tx*2+1)*132+d4];
            #pragma unroll
            for(int i=0;i<4;i++){
                float4 q4=*(float4*)&sQ[(ty*4+i)*DD+d4];
                acc[i][0]+=q4.x*k0.x+q4.y*k0.y+q4.z*k0.z+q4.w*k0.w;
                acc[i][1]+=q4.x*k1.x+q4.y*k1.y+q4.z*k1.z+q4.w*k1.w;
            }
        }
        #pragma unroll
        for(int i=0;i<4;i++)
            #pragma unroll
            for(int j=0;j<2;j++){
                int t=t0+tx*2+j;
                if(t<len) sS[(ty*4+i)*maxLen+t]=acc[i][j];
            }
        __syncthreads();
    }
    // softmax per row
    int w=tid>>5, lane=tid&31;
    for(int r=w;r<RR;r+=8){
        float* row=sS+(size_t)r*maxLen;
        float m=-1e30f;
        for(int t=lane;t<len;t+=32) m=fmaxf(m,row[t]);
        #pragma unroll
        for(int o=16;o;o>>=1) m=fmaxf(m,__shfl_xor_sync(~0u,m,o));
        float s=0.f;
        for(int t=lane;t<len;t+=32){float e=__expf(row[t]-m); row[t]=e; s+=e;}
        #pragma unroll
        for(int o=16;o;o>>=1) s+=__shfl_xor_sync(~0u,s,o);
        if(lane==0) sInv[r]=1.f/s;
    }
    __syncthreads();
    // phase 2: u = softmax-weighted raw v
    int rg=tid>>4, cg=(tid&15)<<3;
    float acc[4][8]={};
    for(int t0=0;t0<len;t0+=32){
        int tc=min(32,len-t0);
        for(int i=tid;i<tc*32;i+=256){
            int row=i>>5, c4=(i&31)<<2;
            *(float4*)&sT[row*132+c4]=*(const float4*)(vb+(size_t)(s0+t0+row)*DD+c4);
        }
        __syncthreads();
        for(int t=0;t<tc;t++){
            float4 v0=*(float4*)&sT[t*132+cg];
            float4 v1=*(float4*)&sT[t*132+cg+4];
            #pragma unroll
            for(int i=0;i<4;i++){
                float a=sS[(rg*4+i)*maxLen+t0+t];
                acc[i][0]+=a*v0.x; acc[i][1]+=a*v0.y; acc[i][2]+=a*v0.z; acc[i][3]+=a*v0.w;
                acc[i][4]+=a*v1.x; acc[i][5]+=a*v1.y; acc[i][6]+=a*v1.z; acc[i][7]+=a*v1.w;
            }
        }
        __syncthreads();
    }
    #pragma unroll
    for(int i=0;i<4;i++){
        int r=rg*4+i; float iv=sInv[r];
        *(float4*)&ub[(size_t)r*DD+cg]  =make_float4(acc[i][0]*iv,acc[i][1]*iv,acc[i][2]*iv,acc[i][3]*iv);
        *(float4*)&ub[(size_t)r*DD+cg+4]=make_float4(acc[i][4]*iv,acc[i][5]*iv,acc[i][6]*iv,acc[i][7]*iv);
    }
}

__global__ void __launch_bounds__(128) k_head2(const float* h,const float* w2,const float* b2,float* out){
    int b=blockIdx.x, c=threadIdx.x;
    float s=h[(size_t)b*DD+c]*w2[c];
    #pragma unroll
    for(int o=16;o;o>>=1) s+=__shfl_xor_sync(~0u,s,o);
    __shared__ float red[4];
    if((c&31)==0) red[c>>5]=s;
    __syncthreads();
    if(c==0){
        float t=red[0]+red[1]+red[2]+red[3]+b2[0];
        out[b]=fmaxf(t,0.f)+log1pf(__expf(-fabsf(t)));
    }
}

extern "C" void kernel_launch(void* const* d_in, const int* in_sizes, int n_in,
                              void* d_out, int out_size){
    (void)in_sizes;(void)n_in;(void)out_size;
    const float* drug_k=(const float*)d_in[0];
    const float* drug_v=(const float*)d_in[1];
    const float* enz_k =(const float*)d_in[2];
    const float* enz_v =(const float*)d_in[3];
    const int*   db    =(const int*)d_in[4];
    const int*   eb    =(const int*)d_in[5];
    const float* lat   =(const float*)d_in[6];
    const float* wq_d=(const float*)d_in[7];  const float* bq_d=(const float*)d_in[8];
    const float* wq_e=(const float*)d_in[9];  const float* bq_e=(const float*)d_in[10];
    const float* mw_d=(const float*)d_in[11]; const float* mb_d=(const float*)d_in[12];
    const float* ow_d=(const float*)d_in[13]; const float* ob_d=(const float*)d_in[14];
    const float* mw_e=(const float*)d_in[15]; const float* mb_e=(const float*)d_in[16];
    const float* ow_e=(const float*)d_in[17]; const float* ob_e=(const float*)d_in[18];
    const float* l1g=(const float*)d_in[19];  const float* l1b=(const float*)d_in[20];
    const float* l2g=(const float*)d_in[21];  const float* l2b=(const float*)d_in[22];
    const float* fw1=(const float*)d_in[23];  const float* fb1=(const float*)d_in[24];
    const float* fw2=(const float*)d_in[25];  const float* fb2=(const float*)d_in[26];
    const float* hw1=(const float*)d_in[27];  const float* hb1=(const float*)d_in[28];
    const float* hw2=(const float*)d_in[29];  const float* hb2=(const float*)d_in[30];
    float* out=(float*)d_out;

    static float *p_lat,*p_nl,*p_qp,*p_u,*p_ffh,*p_h,*p_P,*p_M,*p_pb,*p_mb; static int* p_st;
    static bool init=false;
    if(!init){
        cudaGetSymbolAddress((void**)&p_lat,g_lat); cudaGetSymbolAddress((void**)&p_nl,g_nl);
        cudaGetSymbolAddress((void**)&p_qp,g_qp);   cudaGetSymbolAddress((void**)&p_u,g_u);
        cudaGetSymbolAddress((void**)&p_ffh,g_ffh); cudaGetSymbolAddress((void**)&p_h,g_h);
        cudaGetSymbolAddress((void**)&p_P,g_P);     cudaGetSymbolAddress((void**)&p_M,g_M);
        cudaGetSymbolAddress((void**)&p_pb,g_pb);   cudaGetSymbolAddress((void**)&p_mb,g_mb);
        cudaGetSymbolAddress((void**)&p_st,g_st);
        cudaFuncSetAttribute(k_attn,cudaFuncAttributeMaxDynamicSharedMemorySize,182000);
        init=true;
    }
    k_starts<<<1,1024>>>(db,eb);
    k_pre<<<32,256>>>(mw_d,mb_d,ow_d,ob_d,mw_e,mb_e,ow_e,ob_e);
    k_init<<<1024,256>>>(lat);

    const int smemD=(RR*DD+RR*128+32*132)*4;
    const int smemE=(RR*DD+RR*512+32*132)*4;
    for(int l=0;l<NLAYER;l++){
        k_ln<<<1024,256>>>(p_lat,p_nl,l1g+l*DD,l1b+l*DD);
        for(int m=0;m<2;m++){
            const float* wq =m?wq_e:wq_d;  const float* bq=m?bq_e:bq_d;
            const float* kb =m?enz_k:drug_k; const float* vb=m?enz_v:drug_v;
            const int* st = p_st + m*(BB+1);
            int maxLen = m?512:128;
            int smem = m?smemE:smemD;
            // q = nl @ wq^T + bq
            k_gemm<false,false,false><<<dim3(128,2),256>>>(p_nl,DD,wq+l*DD*DD,DD,p_ffh,DD,bq+l*DD,8192,DD,DD);
            // qp = q @ Pcat + pbias
            k_gemm<true,false,false><<<dim3(128,8),256>>>(p_ffh,DD,p_P+(l*2+m)*DD*512,512,p_qp,512,p_pb+(l*2+m)*512,8192,512,DD);
            k_attn<<<BB,256,smem>>>(p_qp,kb,vb,st,p_u,maxLen);
            // lat += u @ Mcat^T + mbias
            k_gemm<false,true,false><<<dim3(128,2),256>>>(p_u,512,p_M+(l*2+m)*DD*512,512,p_lat,DD,p_mb+(l*2+m)*DD,8192,DD,512);
        }
        k_ln<<<1024,256>>>(p_lat,p_nl,l2g+l*DD,l2b+l*DD);
        k_gemm<false,false,true><<<dim3(128,4),256>>>(p_nl,DD,fw1+l*2*DD*DD,DD,p_ffh,2*DD,fb1+l*2*DD,8192,2*DD,DD);
        k_gemm<false,true,false><<<dim3(128,2),256>>>(p_ffh,2*DD,fw2+l*2*DD*DD,2*DD,p_lat,DD,fb2+l*DD,8192,DD,2*DD);
    }
    k_gemm<false,false,true><<<dim3(8,2),256>>>(p_lat,NLAT*DD,hw1,NLAT*DD,p_h,DD,hb1,BB,DD,NLAT*DD);
    k_head2<<<BB,128>>>(p_h,hw2,hb2,out);
}

// round 4
// speedup vs baseline: 1.1967x; 1.1967x over previous
#include <cuda_runtime.h>
#include <math.h>

#define BB 512
#define DD 128
#define NLAT 16
#define NLAYER 4
#define NDRUG 25600
#define NENZ 153600
#define RR 64  // NL*H rows per batch

__device__ float g_lat[BB*NLAT*DD];
__device__ float g_nl [BB*NLAT*DD];
__device__ float g_qp [BB*RR*DD];
__device__ float g_u  [BB*RR*DD];
__device__ float g_ffh[BB*NLAT*2*DD];
__device__ float g_h  [BB*DD];
__device__ float g_P  [8*DD*512];
__device__ float g_M  [8*DD*512];
__device__ float g_pb [8*512];
__device__ float g_mb [8*DD];
__device__ int   g_st [2*(BB+1)];

// ---- packed f32x2 helpers (FFMA2: 2 MACs/instr, fma pipe full rate) ----
typedef unsigned long long ull;
__device__ __forceinline__ void ffma2(ull &d, ull a, ull b){
    asm("fma.rn.f32x2 %0, %1, %2, %0;" : "+l"(d) : "l"(a), "l"(b));
}
__device__ __forceinline__ void mul2(ull &d, ull s){
    asm("mul.rn.f32x2 %0, %0, %1;" : "+l"(d) : "l"(s));
}
__device__ __forceinline__ ull dup2(float a){
    ull r; asm("mov.b64 %0, {%1,%1};" : "=l"(r) : "f"(a)); return r;
}
__device__ __forceinline__ float2 unp(ull v){
    float2 f; asm("mov.b64 {%0,%1}, %2;" : "=f"(f.x), "=f"(f.y) : "l"(v)); return f;
}

__device__ __forceinline__ int lowb(const int* a, int n, int v){
    int lo=0, hi=n;
    while(lo<hi){int mid=(lo+hi)>>1; if(a[mid]<v) lo=mid+1; else hi=mid;}
    return lo;
}

__global__ void k_starts(const int* db, const int* eb){
    int b=threadIdx.x;
    if(b<BB){ g_st[b]=lowb(db,NDRUG,b); g_st[BB+1+b]=lowb(eb,NENZ,b); }
    if(b==0){ g_st[BB]=NDRUG; g_st[2*BB+1]=NENZ; }
    if(b<1024) g_mb[b]=0.f;
}

__global__ void k_init(const float* lat){
    int i=blockIdx.x*256+threadIdx.x;
    ((float4*)g_lat)[i]=((const float4*)lat)[i&511];
}

// weight precompute: P_h = Wqm_h^T Wk_h / sqrt(HD); M_h = Wo_h Wv_h; biases
__global__ void k_pre(const float* mwd,const float* mbd,const float* owd,const float* obd,
                      const float* mwe,const float* mbe,const float* owe,const float* obe){
    int idx=blockIdx.x, l=idx>>3, m=(idx>>2)&1, h=idx&3;
    const float* w =(m?mwe:mwd)+l*3*DD*DD;
    const float* b3=(m?mbe:mbd)+l*3*DD;
    const float* ow=(m?owe:owd)+l*DD*DD;
    const float* ob=(m?obe:obd)+l*DD;
    float* P=g_P+(l*2+m)*DD*512; float* M=g_M+(l*2+m)*DD*512;
    float* pb=g_pb+(l*2+m)*512;
    __shared__ float sA[32*128], sB[32*128];
    int tid=threadIdx.x;
    const float inv=0.17677669529663687f; // 1/sqrt(32)
    for(int i=tid;i<32*128;i+=256){int j=i>>7,c=i&127;
        sA[i]=w[(h*32+j)*DD+c]; sB[i]=w[(DD+h*32+j)*DD+c];}
    __syncthreads();
    for(int e=tid;e<128*128;e+=256){int c=e>>7,d=e&127; float s=0.f;
        #pragma unroll
        for(int j=0;j<32;j++) s+=sA[j*128+c]*sB[j*128+d];
        P[c*512+h*128+d]=s*inv;}
    if(tid<128){float s=0.f;
        for(int j=0;j<32;j++) s+=b3[h*32+j]*sB[j*128+tid];
        pb[h*128+tid]=s*inv;}
    __syncthreads();
    for(int i=tid;i<32*128;i+=256){int j=i>>7,c=i&127; sB[i]=w[(2*DD+h*32+j)*DD+c];}
    for(int i=tid;i<128*32;i+=256){int c=i>>5,j=i&31; sA[c*32+j]=ow[c*DD+h*32+j];}
    __syncthreads();
    for(int e=tid;e<128*128;e+=256){int c=e>>7,d=e&127; float s=0.f;
        #pragma unroll
        for(int j=0;j<32;j++) s+=sA[c*32+j]*sB[j*128+d];
        M[c*512+h*128+d]=s;}
    if(tid<128){float s=(h==0)?ob[tid]:0.f;
        for(int j=0;j<32;j++) s+=sA[tid*32+j]*b3[2*DD+h*32+j];
        atomicAdd(&g_mb[(l*2+m)*DD+tid],s);}
}

// layernorm: 1 warp per 128-d row
__global__ void __launch_bounds__(256) k_ln(const float* x,float* y,const float* g,const float* bb){
    int row=blockIdx.x*8+(threadIdx.x>>5), lane=threadIdx.x&31;
    float4 v=*(const float4*)(x+(size_t)row*DD+lane*4);
    float s=v.x+v.y+v.z+v.w, s2=v.x*v.x+v.y*v.y+v.z*v.z+v.w*v.w;
    #pragma unroll
    for(int o=16;o;o>>=1){s+=__shfl_xor_sync(~0u,s,o); s2+=__shfl_xor_sync(~0u,s2,o);}
    float m=s*(1.f/128.f), var=s2*(1.f/128.f)-m*m, iv=rsqrtf(var+1e-5f);
    float4 gg=*(const float4*)(g+lane*4), b4=*(const float4*)(bb+lane*4);
    float4 o;
    o.x=(v.x-m)*iv*gg.x+b4.x; o.y=(v.y-m)*iv*gg.y+b4.y;
    o.z=(v.z-m)*iv*gg.z+b4.z; o.w=(v.w-m)*iv*gg.w+b4.w;
    *(float4*)(y+(size_t)row*DD+lane*4)=o;
}

// tiled GEMM with FFMA2: C[r,c] (opt +=) = act(sum_k A[r,k]*W(c,k) + bias[c])
template<bool WT,bool ACC,bool RELU>
__global__ void __launch_bounds__(256) k_gemm(const float* A,int lda,const float* W,int ldw,
                                              float* C,int ldc,const float* bias,
                                              int M,int N,int K){
    __shared__ float sA[32*68], sB[32*68];
    int rb=blockIdx.x*64, cb=blockIdx.y*64, tid=threadIdx.x;
    int tx=tid&15, ty=tid>>4;
    ull acc2[2][4]={};   // row-pairs (ty*4+0,1),(ty*4+2,3) x 4 cols
    for(int k0=0;k0<K;k0+=32){
        #pragma unroll
        for(int it=0;it<2;it++){
            int i=tid+it*256, row=i>>3, q4=(i&7)<<2;
            float4 a4=*(const float4*)(A+(size_t)(rb+row)*lda+k0+q4);
            sA[(q4+0)*68+row]=a4.x; sA[(q4+1)*68+row]=a4.y;
            sA[(q4+2)*68+row]=a4.z; sA[(q4+3)*68+row]=a4.w;
        }
        if(!WT){
            #pragma unroll
            for(int it=0;it<2;it++){
                int i=tid+it*256, row=i>>3, q4=(i&7)<<2, c=cb+row;
                float4 w4=make_float4(0.f,0.f,0.f,0.f);
                if(c<N) w4=*(const float4*)(W+(size_t)c*ldw+k0+q4);
                sB[(q4+0)*68+row]=w4.x; sB[(q4+1)*68+row]=w4.y;
                sB[(q4+2)*68+row]=w4.z; sB[(q4+3)*68+row]=w4.w;
            }
        }else{
            #pragma unroll
            for(int it=0;it<2;it++){
                int i=tid+it*256, kr=i>>4, cc=(i&15)<<2;
                float4 w4=make_float4(0.f,0.f,0.f,0.f);
                if(cb+cc<N) w4=*(const float4*)(W+(size_t)(k0+kr)*ldw+cb+cc);
                *(float4*)&sB[kr*68+cc]=w4;
            }
        }
        __syncthreads();
        #pragma unroll 8
        for(int kk=0;kk<32;kk++){
            ulonglong2 a2=*(ulonglong2*)&sA[kk*68+ty*4];
            float4 b4=*(float4*)&sB[kk*68+tx*4];
            ull b0=dup2(b4.x), b1=dup2(b4.y), b2=dup2(b4.z), b3=dup2(b4.w);
            ffma2(acc2[0][0],a2.x,b0); ffma2(acc2[0][1],a2.x,b1);
            ffma2(acc2[0][2],a2.x,b2); ffma2(acc2[0][3],a2.x,b3);
            ffma2(acc2[1][0],a2.y,b0); ffma2(acc2[1][1],a2.y,b1);
            ffma2(acc2[1][2],a2.y,b2); ffma2(acc2[1][3],a2.y,b3);
        }
        __syncthreads();
    }
    #pragma unroll
    for(int rp=0;rp<2;rp++){
        int r0=rb+ty*4+rp*2;
        #pragma unroll
        for(int j=0;j<4;j++){
            int c=cb+tx*4+j;
            if(c<N){
                float2 f=unp(acc2[rp][j]);
                float bv=bias[c];
                float v0=f.x+bv, v1=f.y+bv;
                if(ACC){ v0+=C[(size_t)r0*ldc+c]; v1+=C[(size_t)(r0+1)*ldc+c]; }
                if(RELU){ v0=fmaxf(v0,0.f); v1=fmaxf(v1,0.f); }
                C[(size_t)r0*ldc+c]=v0;
                C[(size_t)(r0+1)*ldc+c]=v1;
            }
        }
    }
}

// flash-style ragged cross-attention on raw tokens. qp/u: [B][64][128]
// smem: sQ[64*128] + sKV[32*132] (K then V, reused) + sS[64*32]
__global__ void __launch_bounds__(256) k_attn(const float* qp,const float* kb,const float* vb,
                                              const int* starts,float* u,int maxLen){
    extern __shared__ float sm[];
    float* sQ=sm;                 // 8192
    float* sKV=sm+RR*DD;          // 32*132
    float* sS=sKV+32*132;         // 64*32
    __shared__ float sM[RR], sSum[RR], sScale[RR];
    int b=blockIdx.x, tid=threadIdx.x;
    int s0=starts[b], len=starts[b+1]-s0;
    if(len>maxLen) len=maxLen;
    const float* qpb=qp+(size_t)b*RR*DD;
    float* ub=u+(size_t)b*RR*DD;
    if(len==0){
        for(int i=tid;i<RR*DD/4;i+=256) ((float4*)ub)[i]=make_float4(0.f,0.f,0.f,0.f);
        return;
    }
    for(int i=tid;i<RR*DD/4;i+=256) ((float4*)sQ)[i]=((const float4*)qpb)[i];
    if(tid<RR){ sM[tid]=-1e30f; sSum[tid]=0.f; }
    __syncthreads();

    int ty=tid>>4, tx=tid&15;      // scores: rows ty*4+i, tokens tx*2+j
    int rg=tid>>4, cg=(tid&15)<<3; // V: rows rg*4+i, cols cg..cg+7
    int w=tid>>5, lane=tid&31;
    ull acc[4][4]={};              // V accumulator (col pairs)

    for(int t0=0;t0<len;t0+=32){
        int tc=min(32,len-t0);
        // load K tile
        for(int i=tid;i<tc*32;i+=256){
            int row=i>>5, c4=(i&31)<<2;
            *(float4*)&sKV[row*132+c4]=*(const float4*)(kb+(size_t)(s0+t0+row)*DD+c4);
        }
        __syncthreads();
        // scores: pair over reduction dim d (no dups needed)
        {
            ull sc2[4][2]={};
            #pragma unroll 8
            for(int d=0;d<DD;d+=4){
                ulonglong2 k0=*(ulonglong2*)&sKV[(tx*2)*132+d];
                ulonglong2 k1=*(ulonglong2*)&sKV[(tx*2+1)*132+d];
                #pragma unroll
                for(int i=0;i<4;i++){
                    ulonglong2 q2=*(ulonglong2*)&sQ[(ty*4+i)*DD+d];
                    ffma2(sc2[i][0],q2.x,k0.x); ffma2(sc2[i][0],q2.y,k0.y);
                    ffma2(sc2[i][1],q2.x,k1.x); ffma2(sc2[i][1],q2.y,k1.y);
                }
            }
            #pragma unroll
            for(int i=0;i<4;i++)
                #pragma unroll
                for(int j=0;j<2;j++){
                    int t=tx*2+j;
                    float2 f=unp(sc2[i][j]);
                    sS[(ty*4+i)*32+t]=(t<tc)?(f.x+f.y):-1e30f;
                }
        }
        __syncthreads();
        // online softmax update (8 warps x 8 rows each)
        for(int r=w;r<RR;r+=8){
            float x=sS[r*32+lane];
            float tm=x;
            #pragma unroll
            for(int o=16;o;o>>=1) tm=fmaxf(tm,__shfl_xor_sync(~0u,tm,o));
            float mOld=sM[r], mNew=fmaxf(mOld,tm);
            float e=__expf(x-mNew);
            float ts=e;
            #pragma unroll
            for(int o=16;o;o>>=1) ts+=__shfl_xor_sync(~0u,ts,o);
            sS[r*32+lane]=e;
            if(lane==0){
                float sc=__expf(mOld-mNew);
                sScale[r]=sc;
                sSum[r]=sSum[r]*sc+ts;
                sM[r]=mNew;
            }
        }
        // load V tile into same buffer (safe: K reads finished before prior sync)
        for(int i=tid;i<tc*32;i+=256){
            int row=i>>5, c4=(i&31)<<2;
            *(float4*)&sKV[row*132+c4]=*(const float4*)(vb+(size_t)(s0+t0+row)*DD+c4);
        }
        __syncthreads();
        // rescale accumulator and add exp-weighted V
        #pragma unroll
        for(int i=0;i<4;i++){
            ull sc2=dup2(sScale[rg*4+i]);
            #pragma unroll
            for(int p=0;p<4;p++) mul2(acc[i][p],sc2);
        }
        for(int t=0;t<tc;t++){
            ulonglong2 v0=*(ulonglong2*)&sKV[t*132+cg];
            ulonglong2 v1=*(ulonglong2*)&sKV[t*132+cg+4];
            #pragma unroll
            for(int i=0;i<4;i++){
                ull a2=dup2(sS[(rg*4+i)*32+t]);
                ffma2(acc[i][0],a2,v0.x); ffma2(acc[i][1],a2,v0.y);
                ffma2(acc[i][2],a2,v1.x); ffma2(acc[i][3],a2,v1.y);
            }
        }
        __syncthreads();
    }
    #pragma unroll
    for(int i=0;i<4;i++){
        int r=rg*4+i;
        float iv=1.f/sSum[r];
        float2 f0=unp(acc[i][0]), f1=unp(acc[i][1]), f2=unp(acc[i][2]), f3=unp(acc[i][3]);
        *(float4*)&ub[(size_t)r*DD+cg]  =make_float4(f0.x*iv,f0.y*iv,f1.x*iv,f1.y*iv);
        *(float4*)&ub[(size_t)r*DD+cg+4]=make_float4(f2.x*iv,f2.y*iv,f3.x*iv,f3.y*iv);
    }
}

__global__ void __launch_bounds__(128) k_head2(const float* h,const float* w2,const float* b2,float* out){
    int b=blockIdx.x, c=threadIdx.x;
    float s=h[(size_t)b*DD+c]*w2[c];
    #pragma unroll
    for(int o=16;o;o>>=1) s+=__shfl_xor_sync(~0u,s,o);
    __shared__ float red[4];
    if((c&31)==0) red[c>>5]=s;
    __syncthreads();
    if(c==0){
        float t=red[0]+red[1]+red[2]+red[3]+b2[0];
        out[b]=fmaxf(t,0.f)+log1pf(__expf(-fabsf(t)));
    }
}

extern "C" void kernel_launch(void* const* d_in, const int* in_sizes, int n_in,
                              void* d_out, int out_size){
    (void)in_sizes;(void)n_in;(void)out_size;
    const float* drug_k=(const float*)d_in[0];
    const float* drug_v=(const float*)d_in[1];
    const float* enz_k =(const float*)d_in[2];
    const float* enz_v =(const float*)d_in[3];
    const int*   db    =(const int*)d_in[4];
    const int*   eb    =(const int*)d_in[5];
    const float* lat   =(const float*)d_in[6];
    const float* wq_d=(const float*)d_in[7];  const float* bq_d=(const float*)d_in[8];
    const float* wq_e=(const float*)d_in[9];  const float* bq_e=(const float*)d_in[10];
    const float* mw_d=(const float*)d_in[11]; const float* mb_d=(const float*)d_in[12];
    const float* ow_d=(const float*)d_in[13]; const float* ob_d=(const float*)d_in[14];
    const float* mw_e=(const float*)d_in[15]; const float* mb_e=(const float*)d_in[16];
    const float* ow_e=(const float*)d_in[17]; const float* ob_e=(const float*)d_in[18];
    const float* l1g=(const float*)d_in[19];  const float* l1b=(const float*)d_in[20];
    const float* l2g=(const float*)d_in[21];  const float* l2b=(const float*)d_in[22];
    const float* fw1=(const float*)d_in[23];  const float* fb1=(const float*)d_in[24];
    const float* fw2=(const float*)d_in[25];  const float* fb2=(const float*)d_in[26];
    const float* hw1=(const float*)d_in[27];  const float* hb1=(const float*)d_in[28];
    const float* hw2=(const float*)d_in[29];  const float* hb2=(const float*)d_in[30];
    float* out=(float*)d_out;

    static float *p_lat,*p_nl,*p_qp,*p_u,*p_ffh,*p_h,*p_P,*p_M,*p_pb,*p_mb; static int* p_st;
    static bool init=false;
    if(!init){
        cudaGetSymbolAddress((void**)&p_lat,g_lat); cudaGetSymbolAddress((void**)&p_nl,g_nl);
        cudaGetSymbolAddress((void**)&p_qp,g_qp);   cudaGetSymbolAddress((void**)&p_u,g_u);
        cudaGetSymbolAddress((void**)&p_ffh,g_ffh); cudaGetSymbolAddress((void**)&p_h,g_h);
        cudaGetSymbolAddress((void**)&p_P,g_P);     cudaGetSymbolAddress((void**)&p_M,g_M);
        cudaGetSymbolAddress((void**)&p_pb,g_pb);   cudaGetSymbolAddress((void**)&p_mb,g_mb);
        cudaGetSymbolAddress((void**)&p_st,g_st);
        cudaFuncSetAttribute(k_attn,cudaFuncAttributeMaxDynamicSharedMemorySize,60000);
        init=true;
    }
    k_starts<<<1,1024>>>(db,eb);
    k_pre<<<32,256>>>(mw_d,mb_d,ow_d,ob_d,mw_e,mb_e,ow_e,ob_e);
    k_init<<<1024,256>>>(lat);

    const int smemA=(RR*DD+32*132+RR*32)*4;  // 57856
    for(int l=0;l<NLAYER;l++){
        k_ln<<<1024,256>>>(p_lat,p_nl,l1g+l*DD,l1b+l*DD);
        for(int m=0;m<2;m++){
            const float* wq =m?wq_e:wq_d;  const float* bq=m?bq_e:bq_d;
            const float* kb =m?enz_k:drug_k; const float* vb=m?enz_v:drug_v;
            const int* st = p_st + m*(BB+1);
            int maxLen = m?512:128;
            // q = nl @ wq^T + bq
            k_gemm<false,false,false><<<dim3(128,2),256>>>(p_nl,DD,wq+l*DD*DD,DD,p_ffh,DD,bq+l*DD,8192,DD,DD);
            // qp = q @ Pcat + pbias
            k_gemm<true,false,false><<<dim3(128,8),256>>>(p_ffh,DD,p_P+(l*2+m)*DD*512,512,p_qp,512,p_pb+(l*2+m)*512,8192,512,DD);
            k_attn<<<BB,256,smemA>>>(p_qp,kb,vb,st,p_u,maxLen);
            // lat += u @ Mcat^T + mbias
            k_gemm<false,true,false><<<dim3(128,2),256>>>(p_u,512,p_M+(l*2+m)*DD*512,512,p_lat,DD,p_mb+(l*2+m)*DD,8192,DD,512);
        }
        k_ln<<<1024,256>>>(p_lat,p_nl,l2g+l*DD,l2b+l*DD);
        k_gemm<false,false,true><<<dim3(128,4),256>>>(p_nl,DD,fw1+l*2*DD*DD,DD,p_ffh,2*DD,fb1+l*2*DD,8192,2*DD,DD);
        k_gemm<false,true,false><<<dim3(128,2),256>>>(p_ffh,2*DD,fw2+l*2*DD*DD,2*DD,p_lat,DD,fb2+l*DD,8192,DD,2*DD);
    }
    k_gemm<false,false,true><<<dim3(8,2),256>>>(p_lat,NLAT*DD,hw1,NLAT*DD,p_h,DD,hb1,BB,DD,NLAT*DD);
    k_head2<<<BB,128>>>(p_h,hw2,hb2,out);
}